// round 1
// baseline (speedup 1.0000x reference)
#include <cuda_runtime.h>
#include <cstdint>

// Problem constants (fixed shapes from reference)
#define B_ROWS 16384
#define T_LEN  4096
#define WORDS  (T_LEN / 32)   // 128 mask words per row
#define THREADS 256

__global__ void __launch_bounds__(THREADS, 8)
yawning_adjust_kernel(const float* __restrict__ drowsiness,
                      const int* __restrict__ gesture,
                      float* __restrict__ out)
{
    const int row = blockIdx.x;
    const int* __restrict__ grow = gesture + (size_t)row * T_LEN;

    __shared__ uint32_t smask[WORDS];
    __shared__ int sred[THREADS / 32];

    const int lane = threadIdx.x & 31;
    const int warp = threadIdx.x >> 5;   // 0..7

    // Phase 1: build packed yawning mask. Each warp covers WORDS/8 = 16 words.
    // Lane l of warp w at iter i reads element ((i*8 + w)*32 + l): consecutive
    // lanes -> consecutive addresses -> fully coalesced 128B/warp transactions.
#pragma unroll
    for (int i = 0; i < WORDS / 8; i++) {
        const int w = i * 8 + warp;
        const int v = grow[w * 32 + lane];
        const uint32_t b = __ballot_sync(0xffffffffu, v == 2);
        if (lane == 0) smask[w] = b;
    }
    __syncthreads();

    // Phase 2: per-word streak counting.
    // A streak of length >= L exists iff some start position t (m[t] && !m[t-1])
    // has m[t..t+L-1] all set. Window <= 7 bits ahead, 1 bit behind.
    int packed = 0;  // hc | (lc << 16); per-row counts < 820 so 16 bits suffice
    if (threadIdx.x < WORDS) {
        const int w = threadIdx.x;
        const uint32_t M       = smask[w];
        const uint32_t nxt     = (w + 1 < WORDS) ? smask[w + 1] : 0u;
        const uint32_t prevbit = (w > 0) ? (smask[w - 1] >> 31) : 0u;

        const uint64_t ext = ((uint64_t)nxt << 32) | (uint64_t)M;
        const uint32_t starts = M & ~((M << 1) | prevbit);

        const uint64_t r4 = ext & (ext >> 1) & (ext >> 2) & (ext >> 3);
        const uint64_t r7 = r4  & (ext >> 4) & (ext >> 5) & (ext >> 6);

        const int hc = __popc(starts & (uint32_t)r4);
        const int lc = __popc(starts & (uint32_t)r7);
        packed = hc | (lc << 16);
    }

    // Phase 3: block reduction of packed counts.
#pragma unroll
    for (int off = 16; off > 0; off >>= 1)
        packed += __shfl_down_sync(0xffffffffu, packed, off);
    if (lane == 0) sred[warp] = packed;
    __syncthreads();

    if (threadIdx.x == 0) {
        int tot = 0;
#pragma unroll
        for (int i = 0; i < THREADS / 32; i++) tot += sred[i];
        const int hc = tot & 0xffff;
        const int lc = tot >> 16;

        float hadj = (hc >= 2) ? 0.18f * expf(-0.5f * (float)(hc - 2)) : 0.0f;
        float ladj = (lc >= 3) ? 0.05f * expf(-0.5f * (float)(lc - 3)) : 0.0f;
        float adj = fminf(hadj + ladj, 0.35f);
        float r = drowsiness[row] + adj;
        out[row] = fminf(fmaxf(r, 0.0f), 1.0f);
    }
}

extern "C" void kernel_launch(void* const* d_in, const int* in_sizes, int n_in,
                              void* d_out, int out_size)
{
    const float* drowsiness = (const float*)d_in[0];   // [B, 1] fp32
    const int*   gesture    = (const int*)d_in[1];     // [B, T, 1] int32
    float*       out        = (float*)d_out;           // [B, 1] fp32
    (void)in_sizes; (void)n_in; (void)out_size;

    yawning_adjust_kernel<<<B_ROWS, THREADS>>>(drowsiness, gesture, out);
}

// round 2
// speedup vs baseline: 1.0059x; 1.0059x over previous
#include <cuda_runtime.h>
#include <cstdint>

// Problem constants (fixed shapes from reference)
#define B_ROWS 16384
#define T_LEN  4096
#define WORDS  (T_LEN / 32)   // 128 mask words per row
#define THREADS 256
#define BATCH  8              // loads in flight per thread before consuming

__global__ void __launch_bounds__(THREADS)
yawning_adjust_kernel(const float* __restrict__ drowsiness,
                      const int* __restrict__ gesture,
                      float* __restrict__ out)
{
    const int row = blockIdx.x;
    const int* __restrict__ grow = gesture + (size_t)row * T_LEN;

    __shared__ uint32_t smask[WORDS];
    __shared__ int sred[THREADS / 32];

    const int lane = threadIdx.x & 31;
    const int warp = threadIdx.x >> 5;   // 0..7

    // Phase 1: build packed yawning mask. Each warp covers WORDS/8 = 16 words.
    // Loads are explicitly batched (BATCH independent LDGs issued before any
    // ballot consumes them) so each warp keeps >=8 coalesced loads in flight.
#pragma unroll
    for (int o = 0; o < WORDS / 8; o += BATCH) {
        int v[BATCH];
#pragma unroll
        for (int i = 0; i < BATCH; i++) {
            const int w = (o + i) * 8 + warp;
            v[i] = grow[w * 32 + lane];
        }
#pragma unroll
        for (int i = 0; i < BATCH; i++) {
            const int w = (o + i) * 8 + warp;
            const uint32_t b = __ballot_sync(0xffffffffu, v[i] == 2);
            if (lane == 0) smask[w] = b;
        }
    }
    __syncthreads();

    // Phase 2: per-word streak counting.
    // A streak of length >= L exists iff some start position t (m[t] && !m[t-1])
    // has m[t..t+L-1] all set. Window <= 6 bits ahead, 1 bit behind.
    int packed = 0;  // hc | (lc << 16); per-row counts < 820 so 16 bits suffice
    if (threadIdx.x < WORDS) {
        const int w = threadIdx.x;
        const uint32_t M       = smask[w];
        const uint32_t nxt     = (w + 1 < WORDS) ? smask[w + 1] : 0u;
        const uint32_t prevbit = (w > 0) ? (smask[w - 1] >> 31) : 0u;

        const uint64_t ext = ((uint64_t)nxt << 32) | (uint64_t)M;
        const uint32_t starts = M & ~((M << 1) | prevbit);

        const uint64_t r4 = ext & (ext >> 1) & (ext >> 2) & (ext >> 3);
        const uint64_t r7 = r4  & (ext >> 4) & (ext >> 5) & (ext >> 6);

        const int hc = __popc(starts & (uint32_t)r4);
        const int lc = __popc(starts & (uint32_t)r7);
        packed = hc | (lc << 16);
    }

    // Phase 3: block reduction of packed counts.
#pragma unroll
    for (int off = 16; off > 0; off >>= 1)
        packed += __shfl_down_sync(0xffffffffu, packed, off);
    if (lane == 0) sred[warp] = packed;
    __syncthreads();

    if (threadIdx.x == 0) {
        int tot = 0;
#pragma unroll
        for (int i = 0; i < THREADS / 32; i++) tot += sred[i];
        const int hc = tot & 0xffff;
        const int lc = tot >> 16;

        float hadj = (hc >= 2) ? 0.18f * expf(-0.5f * (float)(hc - 2)) : 0.0f;
        float ladj = (lc >= 3) ? 0.05f * expf(-0.5f * (float)(lc - 3)) : 0.0f;
        float adj = fminf(hadj + ladj, 0.35f);
        float r = drowsiness[row] + adj;
        out[row] = fminf(fmaxf(r, 0.0f), 1.0f);
    }
}

extern "C" void kernel_launch(void* const* d_in, const int* in_sizes, int n_in,
                              void* d_out, int out_size)
{
    const float* drowsiness = (const float*)d_in[0];   // [B, 1] fp32
    const int*   gesture    = (const int*)d_in[1];     // [B, T, 1] int32
    float*       out        = (float*)d_out;           // [B, 1] fp32
    (void)in_sizes; (void)n_in; (void)out_size;

    yawning_adjust_kernel<<<B_ROWS, THREADS>>>(drowsiness, gesture, out);
}

// round 3
// speedup vs baseline: 1.0491x; 1.0429x over previous
#include <cuda_runtime.h>
#include <cstdint>

// Problem constants (fixed shapes from reference)
#define B_ROWS 16384
#define T_LEN  4096
#define WORDS  (T_LEN / 32)    // 128 mask words per row
#define CHUNKS (T_LEN / 128)   // 32 warp-chunks (128 elems each) per row
#define THREADS 256

// Spread 8 bits (positions 0..7) to positions 0,4,8,...,28.
__device__ __forceinline__ uint32_t spread4(uint32_t x)
{
    x &= 0xffu;
    x = (x | (x << 12)) & 0x000F000Fu;
    x = (x | (x << 6))  & 0x03030303u;
    x = (x | (x << 3))  & 0x11111111u;
    return x;
}

__global__ void __launch_bounds__(THREADS)
yawning_adjust_kernel(const float* __restrict__ drowsiness,
                      const int* __restrict__ gesture,
                      float* __restrict__ out)
{
    const int row = blockIdx.x;
    const int4* __restrict__ grow4 =
        (const int4*)(gesture + (size_t)row * T_LEN);

    __shared__ uint32_t sball[CHUNKS * 4];  // raw interleaved ballots
    __shared__ uint32_t smask[WORDS];       // contiguous mask words
    __shared__ int sred[THREADS / 32];

    const int lane = threadIdx.x & 31;
    const int warp = threadIdx.x >> 5;   // 0..7

    // ── Phase 1: wide streaming loads + ballot packing ────────────────────
    // Each warp covers 4 chunks of 128 elements. Lane l loads int4 at
    // element c*128 + l*4 (LDG.128, fully coalesced, evict-first).
    int4 g[4];
#pragma unroll
    for (int i = 0; i < 4; i++) {
        const int c = i * 8 + warp;
        g[i] = __ldcs(&grow4[c * 32 + lane]);
    }
#pragma unroll
    for (int i = 0; i < 4; i++) {
        const int c = i * 8 + warp;
        const uint32_t b0 = __ballot_sync(0xffffffffu, g[i].x == 2);
        const uint32_t b1 = __ballot_sync(0xffffffffu, g[i].y == 2);
        const uint32_t b2 = __ballot_sync(0xffffffffu, g[i].z == 2);
        const uint32_t b3 = __ballot_sync(0xffffffffu, g[i].w == 2);
        if (lane == 0) {
            sball[c * 4 + 0] = b0;
            sball[c * 4 + 1] = b1;
            sball[c * 4 + 2] = b2;
            sball[c * 4 + 3] = b3;
        }
    }
    __syncthreads();

    // ── Phase 2a: de-interleave ballots into contiguous mask words ───────
    // Word w covers elements [w*32, w*32+32). Within chunk c = w/4, its bits
    // come from lanes 8j..8j+7 (j = w%4) of the 4 ballots: ballot k's lane
    // (8j+i) bit maps to word bit 4i+k.
    if (threadIdx.x < WORDS) {
        const int w = threadIdx.x;
        const int c = w >> 2;
        const int j = w & 3;
        uint32_t word = 0;
#pragma unroll
        for (int k = 0; k < 4; k++) {
            const uint32_t byte = (sball[c * 4 + k] >> (8 * j)) & 0xffu;
            word |= spread4(byte) << k;
        }
        smask[w] = word;
    }
    __syncthreads();

    // ── Phase 2b: per-word streak counting ───────────────────────────────
    // A streak of length >= L exists iff some start position t (m[t] &&
    // !m[t-1]) has m[t..t+L-1] all set. Window <= 6 bits ahead, 1 behind.
    int packed = 0;  // hc | (lc << 16); per-row counts < 820 so 16 bits fit
    if (threadIdx.x < WORDS) {
        const int w = threadIdx.x;
        const uint32_t M       = smask[w];
        const uint32_t nxt     = (w + 1 < WORDS) ? smask[w + 1] : 0u;
        const uint32_t prevbit = (w > 0) ? (smask[w - 1] >> 31) : 0u;

        const uint64_t ext = ((uint64_t)nxt << 32) | (uint64_t)M;
        const uint32_t starts = M & ~((M << 1) | prevbit);

        const uint64_t r4 = ext & (ext >> 1) & (ext >> 2) & (ext >> 3);
        const uint64_t r7 = r4  & (ext >> 4) & (ext >> 5) & (ext >> 6);

        const int hc = __popc(starts & (uint32_t)r4);
        const int lc = __popc(starts & (uint32_t)r7);
        packed = hc | (lc << 16);
    }

    // ── Phase 3: block reduction + epilogue ──────────────────────────────
#pragma unroll
    for (int off = 16; off > 0; off >>= 1)
        packed += __shfl_down_sync(0xffffffffu, packed, off);
    if (lane == 0) sred[warp] = packed;
    __syncthreads();

    if (threadIdx.x == 0) {
        int tot = 0;
#pragma unroll
        for (int i = 0; i < THREADS / 32; i++) tot += sred[i];
        const int hc = tot & 0xffff;
        const int lc = tot >> 16;

        float hadj = (hc >= 2) ? 0.18f * expf(-0.5f * (float)(hc - 2)) : 0.0f;
        float ladj = (lc >= 3) ? 0.05f * expf(-0.5f * (float)(lc - 3)) : 0.0f;
        float adj = fminf(hadj + ladj, 0.35f);
        float r = drowsiness[row] + adj;
        out[row] = fminf(fmaxf(r, 0.0f), 1.0f);
    }
}

extern "C" void kernel_launch(void* const* d_in, const int* in_sizes, int n_in,
                              void* d_out, int out_size)
{
    const float* drowsiness = (const float*)d_in[0];   // [B, 1] fp32
    const int*   gesture    = (const int*)d_in[1];     // [B, T, 1] int32
    float*       out        = (float*)d_out;           // [B, 1] fp32
    (void)in_sizes; (void)n_in; (void)out_size;

    yawning_adjust_kernel<<<B_ROWS, THREADS>>>(drowsiness, gesture, out);
}